// round 13
// baseline (speedup 1.0000x reference)
#include <cuda_runtime.h>

#define SEQ    8192
#define NH     32
#define NKV    8
#define NHT    (NH + NKV)           // 40 heads per token
#define HD     128
#define HALF   64
#define QSIZE  (NH * HD)            // 4096
#define KVSIZE (NKV * HD)           // 1024
#define ROW    (QSIZE + 2 * KVSIZE) // 6144
#define EPSV   1e-6f

#define WARPS_PER_BLOCK 8
#define THREADS 256
#define TASKS_PER_WARP 2            // each task = 2 head-rows (lane-split)

// QK rows: SEQ*NHT = 327680. 4 rows per warp -> 81920 warp-groups -> /8 = 10240 blocks
#define QK_WARPJOBS ((SEQ * NHT) / (2 * TASKS_PER_WARP))
#define QK_BLOCKS   (QK_WARPJOBS / WARPS_PER_BLOCK)
// V copy: SEQ*KVSIZE/4 float4 = 2097152; 2 per thread -> /512 = 4096 blocks
#define V_FLOAT4  ((SEQ * KVSIZE) / 4)
#define V_BLOCKS  (V_FLOAT4 / (THREADS * 2))

__global__ __launch_bounds__(THREADS, 6)
void qknorm_rope_kernel(const float* __restrict__ qkv,
                        const float* __restrict__ qw,
                        const float* __restrict__ kw,
                        const float* __restrict__ cosw,
                        const float* __restrict__ sinw,
                        float* __restrict__ out)
{
    if (blockIdx.x < QK_BLOCKS) {
        const int warp = threadIdx.x >> 5;
        const int lane = threadIdx.x & 31;
        const int job  = blockIdx.x * WARPS_PER_BLOCK + warp;
        const int rbase = job * (2 * TASKS_PER_WARP);   // first of 4 rows
        const int lh   = lane >> 4;                     // 0/1: which row of a task
        const int c    = (lane & 15) * 4;               // column within lo half

        // Minimal state before the loads: only s/h and src pointers.
        int sA[TASKS_PER_WARP], hA[TASKS_PER_WARP];
        const float* src[TASKS_PER_WARP];
        #pragma unroll
        for (int t = 0; t < TASKS_PER_WARP; t++) {
            const int row = rbase + t * 2 + lh;
            const int s = row / NHT;
            const int h = row - s * NHT;
            sA[t] = s; hA[t] = h;
            src[t] = (h < NH)
                   ? qkv + (size_t)s * ROW + h * HD
                   : qkv + (size_t)s * ROW + QSIZE + (h - NH) * HD;
        }

        // 4 independent streaming loads issued back-to-back (MLP_p1 = 4).
        float4 xlo[TASKS_PER_WARP], xhi[TASKS_PER_WARP];
        #pragma unroll
        for (int t = 0; t < TASKS_PER_WARP; t++) {
            xlo[t] = __ldcs(reinterpret_cast<const float4*>(src[t] + c));
            xhi[t] = __ldcs(reinterpret_cast<const float4*>(src[t] + c + HALF));
        }

        float ss[TASKS_PER_WARP];
        #pragma unroll
        for (int t = 0; t < TASKS_PER_WARP; t++)
            ss[t] = xlo[t].x * xlo[t].x + xlo[t].y * xlo[t].y
                  + xlo[t].z * xlo[t].z + xlo[t].w * xlo[t].w
                  + xhi[t].x * xhi[t].x + xhi[t].y * xhi[t].y
                  + xhi[t].z * xhi[t].z + xhi[t].w * xhi[t].w;

        // Interleaved 16-lane butterfly reductions (both tasks pipeline).
        #pragma unroll
        for (int off = 8; off > 0; off >>= 1) {
            #pragma unroll
            for (int t = 0; t < TASKS_PER_WARP; t++)
                ss[t] += __shfl_xor_sync(0xffffffffu, ss[t], off);
        }

        // cos/sin loaded AFTER the reduction: L1-resident, short live range.
        const float4 clo = *reinterpret_cast<const float4*>(cosw + c);
        const float4 chi = *reinterpret_cast<const float4*>(cosw + c + HALF);
        const float4 slo = *reinterpret_cast<const float4*>(sinw + c);
        const float4 shi = *reinterpret_cast<const float4*>(sinw + c + HALF);

        #pragma unroll
        for (int t = 0; t < TASKS_PER_WARP; t++) {
            const float inv = rsqrtf(ss[t] * (1.0f / HD) + EPSV);

            const bool isq = (hA[t] < NH);
            const float* w = isq ? qw : kw;
            float* dst = isq
                ? out + (size_t)sA[t] * QSIZE + hA[t] * HD
                : out + (size_t)SEQ * QSIZE + (size_t)sA[t] * KVSIZE
                      + (hA[t] - NH) * HD;

            const float4 wl = *reinterpret_cast<const float4*>(w + c);
            const float4 wh = *reinterpret_cast<const float4*>(w + c + HALF);

            const float nl0 = xlo[t].x * inv * wl.x, nl1 = xlo[t].y * inv * wl.y;
            const float nl2 = xlo[t].z * inv * wl.z, nl3 = xlo[t].w * inv * wl.w;
            const float nh0 = xhi[t].x * inv * wh.x, nh1 = xhi[t].y * inv * wh.y;
            const float nh2 = xhi[t].z * inv * wh.z, nh3 = xhi[t].w * inv * wh.w;

            float4 olo, ohi;
            olo.x = nl0 * clo.x - nh0 * slo.x;
            olo.y = nl1 * clo.y - nh1 * slo.y;
            olo.z = nl2 * clo.z - nh2 * slo.z;
            olo.w = nl3 * clo.w - nh3 * slo.w;
            ohi.x = nh0 * chi.x + nl0 * shi.x;
            ohi.y = nh1 * chi.y + nl1 * shi.y;
            ohi.z = nh2 * chi.z + nl2 * shi.z;
            ohi.w = nh3 * chi.w + nl3 * shi.w;

            __stcs(reinterpret_cast<float4*>(dst + c), olo);
            __stcs(reinterpret_cast<float4*>(dst + c + HALF), ohi);
        }
    } else {
        // V passthrough: 2 float4 per thread, streaming hints.
        const int vblock = blockIdx.x - QK_BLOCKS;
        const int i0 = vblock * (THREADS * 2) + threadIdx.x;
        const int i1 = i0 + THREADS;
        const float* vbase = qkv + QSIZE + KVSIZE;
        float* vout = out + (size_t)SEQ * (QSIZE + KVSIZE);

        const int s0 = i0 >> 8, c0 = i0 & 255;   // 256 float4 per row
        const int s1 = i1 >> 8, c1 = i1 & 255;

        float4 v0 = __ldcs(reinterpret_cast<const float4*>(vbase + (size_t)s0 * ROW) + c0);
        float4 v1 = __ldcs(reinterpret_cast<const float4*>(vbase + (size_t)s1 * ROW) + c1);
        __stcs(reinterpret_cast<float4*>(vout) + i0, v0);
        __stcs(reinterpret_cast<float4*>(vout) + i1, v1);
    }
}

extern "C" void kernel_launch(void* const* d_in, const int* in_sizes, int n_in,
                              void* d_out, int out_size)
{
    const float* qkv  = (const float*)d_in[0];
    const float* qw   = (const float*)d_in[1];
    const float* kw   = (const float*)d_in[2];
    const float* cosw = (const float*)d_in[3];
    const float* sinw = (const float*)d_in[4];
    float* out = (float*)d_out;

    qknorm_rope_kernel<<<QK_BLOCKS + V_BLOCKS, THREADS>>>(qkv, qw, kw, cosw, sinw, out);
}